// round 2
// baseline (speedup 1.0000x reference)
#include <cuda_runtime.h>
#include <cuda_bf16.h>
#include <math.h>

// Problem constants
#define TT   2048
#define CC   4096
#define NH   32
#define NKV  8
#define HD   128
#define KVC  1024      // NKV*HD
#define HID  11008
#define EPSF 1e-6f

// ---------------- scratch (device globals; no allocation allowed) ----------
__device__ float g_xn [(size_t)TT * CC];   // rmsnorm output (reused for xn2)
__device__ float g_q  [(size_t)TT * CC];
__device__ float g_k  [(size_t)TT * KVC];
__device__ float g_v  [(size_t)TT * KVC];
__device__ float g_s  [(size_t)NH * TT * TT];  // 512MB scores/probs
__device__ float g_att[(size_t)TT * CC];
__device__ float g_x1 [(size_t)TT * CC];
__device__ float g_h1 [(size_t)TT * HID];
__device__ float g_h3 [(size_t)TT * HID];

// ---------------- block reduce helpers -------------------------------------
__device__ __forceinline__ float blockReduceSum256(float v) {
    __shared__ float sh[8];
    int lane = threadIdx.x & 31, w = threadIdx.x >> 5;
    #pragma unroll
    for (int o = 16; o; o >>= 1) v += __shfl_xor_sync(0xffffffffu, v, o);
    if (lane == 0) sh[w] = v;
    __syncthreads();
    float r = sh[0];
    #pragma unroll
    for (int i = 1; i < 8; i++) r += sh[i];
    return r;
}

__device__ __forceinline__ float blockReduceMax256(float v) {
    __shared__ float sh[8];
    int lane = threadIdx.x & 31, w = threadIdx.x >> 5;
    #pragma unroll
    for (int o = 16; o; o >>= 1) v = fmaxf(v, __shfl_xor_sync(0xffffffffu, v, o));
    if (lane == 0) sh[w] = v;
    __syncthreads();
    float r = sh[0];
    #pragma unroll
    for (int i = 1; i < 8; i++) r = fmaxf(r, sh[i]);
    return r;
}

// ---------------- rmsnorm ---------------------------------------------------
__global__ __launch_bounds__(256) void rmsnorm_k(
    const float* __restrict__ x, const float* __restrict__ w,
    float* __restrict__ out)
{
    size_t t = blockIdx.x;
    const float* xr = x + t * CC;
    float ss = 0.f;
    for (int i = threadIdx.x; i < CC; i += 256) { float v = xr[i]; ss += v * v; }
    float tot = blockReduceSum256(ss);
    float inv = rsqrtf(tot * (1.0f / CC) + EPSF);
    for (int i = threadIdx.x; i < CC; i += 256)
        out[t * CC + i] = xr[i] * inv * w[i];
}

// ---------------- rope ------------------------------------------------------
__global__ __launch_bounds__(256) void rope_k(
    float* __restrict__ q, int nheads,
    const float* __restrict__ fc, const float* __restrict__ fs)
{
    int idx = blockIdx.x * 256 + threadIdx.x;
    int total = TT * nheads * (HD / 2);
    if (idx >= total) return;
    int i = idx & 63;
    int h = (idx >> 6) % nheads;
    int t = idx / (64 * nheads);
    float c = fc[t * 64 + i], s = fs[t * 64 + i];
    float* p = q + (size_t)t * nheads * HD + h * HD + 2 * i;
    float re = p[0], im = p[1];
    p[0] = re * c - im * s;
    p[1] = re * s + im * c;
}

// ---------------- softmax (one block per row of 2048) -----------------------
__global__ __launch_bounds__(256) void softmax_k(float* __restrict__ S)
{
    size_t row = blockIdx.x;
    float* r = S + row * TT;
    int tid = threadIdx.x;
    float v[8];
    float mx = -1e30f;
    #pragma unroll
    for (int j = 0; j < 8; j++) { v[j] = r[tid + j * 256]; mx = fmaxf(mx, v[j]); }
    mx = blockReduceMax256(mx);
    float sum = 0.f;
    #pragma unroll
    for (int j = 0; j < 8; j++) { v[j] = __expf(v[j] - mx); sum += v[j]; }
    sum = blockReduceSum256(sum);
    float inv = 1.0f / sum;
    #pragma unroll
    for (int j = 0; j < 8; j++) r[tid + j * 256] = v[j] * inv;
}

// ---------------- silu combine ---------------------------------------------
__global__ __launch_bounds__(256) void silu_k(
    float* __restrict__ h1, const float* __restrict__ h3, size_t n)
{
    size_t i = (size_t)blockIdx.x * 256 + threadIdx.x;
    if (i >= n) return;
    float a = h1[i];
    float s = a / (1.0f + __expf(-a));
    h1[i] = s * h3[i];
}

// ---------------- generic SGEMM --------------------------------------------
// C[M,N] = A[M,K] * op(B) with per-z batch strides.
//   B_KN == false : B is [N,K] row-major (classic "x @ W^T")
//   B_KN == true  : B is [K,N] row-major (P @ V)
// EPI: 0 plain store, 1 add residual R (same ldc indexing), 2 scale+causal mask
#define BM 128
#define BN 128
#define BK 16

template<int EPI, bool B_KN>
__global__ __launch_bounds__(256) void gemm_k(
    int M, int N, int K,
    const float* __restrict__ A, int lda, size_t sA,
    const float* __restrict__ B, int ldb, size_t sB, int bdiv,
    float* __restrict__ Cp, int ldc, size_t sC,
    const float* __restrict__ R, float scale)
{
    __shared__ float As[BK][BM + 4];
    __shared__ float Bs[BK][BN + 4];
    int z = blockIdx.z;
    A  += (size_t)z * sA;
    B  += (size_t)(z / bdiv) * sB;
    Cp += (size_t)z * sC;

    int tid = threadIdx.x;
    int tx = tid & 15, ty = tid >> 4;
    int m0 = blockIdx.y * BM;
    int n0 = blockIdx.x * BN;

    int lr = tid >> 2;          // 0..63
    int lc = (tid & 3) * 4;     // 0,4,8,12
    int br = tid >> 5;          // 0..7
    int bc = (tid & 31) * 4;    // 0..124

    float acc[8][8] = {};

    for (int k0 = 0; k0 < K; k0 += BK) {
        #pragma unroll
        for (int p = 0; p < 2; p++) {
            int m = lr + p * 64;
            float4 a = *(const float4*)&A[(size_t)(m0 + m) * lda + k0 + lc];
            As[lc + 0][m] = a.x; As[lc + 1][m] = a.y;
            As[lc + 2][m] = a.z; As[lc + 3][m] = a.w;
        }
        if (!B_KN) {
            #pragma unroll
            for (int p = 0; p < 2; p++) {
                int n = lr + p * 64;
                float4 b = *(const float4*)&B[(size_t)(n0 + n) * ldb + k0 + lc];
                Bs[lc + 0][n] = b.x; Bs[lc + 1][n] = b.y;
                Bs[lc + 2][n] = b.z; Bs[lc + 3][n] = b.w;
            }
        } else {
            #pragma unroll
            for (int p = 0; p < 2; p++) {
                int k = br + p * 8;
                float4 b = *(const float4*)&B[(size_t)(k0 + k) * ldb + n0 + bc];
                *(float4*)&Bs[k][bc] = b;
            }
        }
        __syncthreads();
        #pragma unroll
        for (int kk = 0; kk < BK; kk++) {
            float a[8], b[8];
            *(float4*)&a[0] = *(const float4*)&As[kk][ty * 8];
            *(float4*)&a[4] = *(const float4*)&As[kk][ty * 8 + 4];
            *(float4*)&b[0] = *(const float4*)&Bs[kk][tx * 8];
            *(float4*)&b[4] = *(const float4*)&Bs[kk][tx * 8 + 4];
            #pragma unroll
            for (int i = 0; i < 8; i++)
                #pragma unroll
                for (int j = 0; j < 8; j++)
                    acc[i][j] += a[i] * b[j];
        }
        __syncthreads();
    }

    #pragma unroll
    for (int i = 0; i < 8; i++) {
        int row = m0 + ty * 8 + i;
        #pragma unroll
        for (int j = 0; j < 8; j++) {
            int col = n0 + tx * 8 + j;
            size_t idx = (size_t)row * ldc + col;
            float v = acc[i][j];
            if (EPI == 1) v += R[idx];
            if (EPI == 2) v = v * scale + (col > row ? -1e9f : 0.0f);
            Cp[idx] = v;
        }
    }
}

// ---------------- launch ----------------------------------------------------
extern "C" void kernel_launch(void* const* d_in, const int* in_sizes, int n_in,
                              void* d_out, int out_size)
{
    const float* x   = (const float*)d_in[0];
    // d_in[1] start_pos (0), d_in[4] mask (causal, applied analytically)
    const float* fc  = (const float*)d_in[2];
    const float* fs  = (const float*)d_in[3];
    const float* wq  = (const float*)d_in[5];
    const float* wk  = (const float*)d_in[6];
    const float* wv  = (const float*)d_in[7];
    const float* wo  = (const float*)d_in[8];
    const float* w1  = (const float*)d_in[9];
    const float* w2  = (const float*)d_in[10];
    const float* w3  = (const float*)d_in[11];
    const float* ln1 = (const float*)d_in[12];
    const float* ln2 = (const float*)d_in[13];
    float* out = (float*)d_out;

    float *xn, *q, *k, *v, *s, *att, *x1, *h1, *h3;
    cudaGetSymbolAddress((void**)&xn,  g_xn);
    cudaGetSymbolAddress((void**)&q,   g_q);
    cudaGetSymbolAddress((void**)&k,   g_k);
    cudaGetSymbolAddress((void**)&v,   g_v);
    cudaGetSymbolAddress((void**)&s,   g_s);
    cudaGetSymbolAddress((void**)&att, g_att);
    cudaGetSymbolAddress((void**)&x1,  g_x1);
    cudaGetSymbolAddress((void**)&h1,  g_h1);
    cudaGetSymbolAddress((void**)&h3,  g_h3);

    const float iscale = 0.08838834764831843f; // 1/sqrt(128)

    // 1) xn = rmsnorm(x, ln1)
    rmsnorm_k<<<TT, 256>>>(x, ln1, xn);

    // 2-4) q/k/v projections
    gemm_k<0,false><<<dim3(CC/BN,  TT/BM, 1), 256>>>(
        TT, CC,  CC, xn, CC, 0, wq, CC, 0, 1, q, CC,  0, nullptr, 0.f);
    gemm_k<0,false><<<dim3(KVC/BN, TT/BM, 1), 256>>>(
        TT, KVC, CC, xn, CC, 0, wk, CC, 0, 1, k, KVC, 0, nullptr, 0.f);
    gemm_k<0,false><<<dim3(KVC/BN, TT/BM, 1), 256>>>(
        TT, KVC, CC, xn, CC, 0, wv, CC, 0, 1, v, KVC, 0, nullptr, 0.f);

    // 5-6) RoPE on q, k
    rope_k<<<(TT * NH  * 64 + 255) / 256, 256>>>(q, NH,  fc, fs);
    rope_k<<<(TT * NKV * 64 + 255) / 256, 256>>>(k, NKV, fc, fs);

    // 7) scores[h] = q_h @ k_{h/4}^T * scale + causal mask
    gemm_k<2,false><<<dim3(TT/BN, TT/BM, NH), 256>>>(
        TT, TT, HD,
        q, CC, (size_t)HD,
        k, KVC, (size_t)HD, 4,
        s, TT, (size_t)TT * TT,
        nullptr, iscale);

    // 8) softmax rows
    softmax_k<<<NH * TT, 256>>>(s);

    // 9) att[h] = P_h @ v_{h/4}
    gemm_k<0,true><<<dim3(HD/BN, TT/BM, NH), 256>>>(
        TT, HD, TT,
        s, TT, (size_t)TT * TT,
        v, KVC, (size_t)HD, 4,
        att, CC, (size_t)HD,
        nullptr, 0.f);

    // 10) x1 = x + att @ wo^T
    gemm_k<1,false><<<dim3(CC/BN, TT/BM, 1), 256>>>(
        TT, CC, CC, att, CC, 0, wo, CC, 0, 1, x1, CC, 0, x, 0.f);

    // 11) xn2 = rmsnorm(x1, ln2)  (reuse g_xn)
    rmsnorm_k<<<TT, 256>>>(x1, ln2, xn);

    // 12-13) h1 = xn2 @ w1^T, h3 = xn2 @ w3^T
    gemm_k<0,false><<<dim3(HID/BN, TT/BM, 1), 256>>>(
        TT, HID, CC, xn, CC, 0, w1, CC, 0, 1, h1, HID, 0, nullptr, 0.f);
    gemm_k<0,false><<<dim3(HID/BN, TT/BM, 1), 256>>>(
        TT, HID, CC, xn, CC, 0, w3, CC, 0, 1, h3, HID, 0, nullptr, 0.f);

    // 14) h1 = silu(h1) * h3
    {
        size_t n = (size_t)TT * HID;
        silu_k<<<(unsigned)((n + 255) / 256), 256>>>(h1, h3, n);
    }

    // 15) out = x1 + h1 @ w2^T
    gemm_k<1,false><<<dim3(CC/BN, TT/BM, 1), 256>>>(
        TT, CC, HID, h1, HID, 0, w2, HID, 0, 1, out, CC, 0, x1, 0.f);
}

// round 4
// speedup vs baseline: 1.4272x; 1.4272x over previous
#include <cuda_runtime.h>
#include <cuda_bf16.h>
#include <mma.h>
#include <cstdint>
#include <math.h>

using namespace nvcuda;

// Problem constants
#define TT   2048
#define CC   4096
#define NH   32
#define NKV  8
#define HD   128
#define KVC  1024
#define HID  11008
#define EPSF 1e-6f

// ---------------- scratch (device globals; no allocation allowed) ----------
__device__ float g_xn [(size_t)TT * CC];
__device__ float g_q  [(size_t)TT * CC];
__device__ float g_k  [(size_t)TT * KVC];
__device__ float g_v  [(size_t)TT * KVC];
__device__ float g_vt [(size_t)NKV * HD * TT];
__device__ float g_s  [(size_t)NH * TT * TT];  // 512MB scores/probs
__device__ float g_att[(size_t)TT * CC];
__device__ float g_x1 [(size_t)TT * CC];
__device__ float g_h1 [(size_t)TT * HID];
__device__ float g_h3 [(size_t)TT * HID];

// =================== elementwise kernels ====================================
__device__ __forceinline__ float blockReduceSum256(float v) {
    __shared__ float sh[8];
    int lane = threadIdx.x & 31, w = threadIdx.x >> 5;
    #pragma unroll
    for (int o = 16; o; o >>= 1) v += __shfl_xor_sync(0xffffffffu, v, o);
    if (lane == 0) sh[w] = v;
    __syncthreads();
    float r = sh[0];
    #pragma unroll
    for (int i = 1; i < 8; i++) r += sh[i];
    return r;
}
__device__ __forceinline__ float blockReduceMax256(float v) {
    __shared__ float sh[8];
    int lane = threadIdx.x & 31, w = threadIdx.x >> 5;
    #pragma unroll
    for (int o = 16; o; o >>= 1) v = fmaxf(v, __shfl_xor_sync(0xffffffffu, v, o));
    if (lane == 0) sh[w] = v;
    __syncthreads();
    float r = sh[0];
    #pragma unroll
    for (int i = 1; i < 8; i++) r = fmaxf(r, sh[i]);
    return r;
}

__global__ __launch_bounds__(256) void rmsnorm_k(
    const float* __restrict__ x, const float* __restrict__ w, float* __restrict__ out)
{
    size_t t = blockIdx.x;
    const float* xr = x + t * CC;
    float ss = 0.f;
    for (int i = threadIdx.x; i < CC; i += 256) { float v = xr[i]; ss += v * v; }
    float tot = blockReduceSum256(ss);
    float inv = rsqrtf(tot * (1.0f / CC) + EPSF);
    for (int i = threadIdx.x; i < CC; i += 256)
        out[t * CC + i] = xr[i] * inv * w[i];
}

// RoPE with optional output scale (folds 1/sqrt(HD) into q)
__global__ __launch_bounds__(256) void rope_k(
    float* __restrict__ q, int nheads,
    const float* __restrict__ fc, const float* __restrict__ fs, float oscale)
{
    int idx = blockIdx.x * 256 + threadIdx.x;
    int total = TT * nheads * (HD / 2);
    if (idx >= total) return;
    int i = idx & 63;
    int h = (idx >> 6) % nheads;
    int t = idx / (64 * nheads);
    float c = fc[t * 64 + i], s = fs[t * 64 + i];
    float* p = q + (size_t)t * nheads * HD + h * HD + 2 * i;
    float re = p[0], im = p[1];
    p[0] = (re * c - im * s) * oscale;
    p[1] = (re * s + im * c) * oscale;
}

__global__ __launch_bounds__(256) void softmax_k(float* __restrict__ S)
{
    size_t row = blockIdx.x;
    float* r = S + row * TT;
    int tid = threadIdx.x;
    float v[8];
    float mx = -1e30f;
    #pragma unroll
    for (int j = 0; j < 8; j++) { v[j] = r[tid + j * 256]; mx = fmaxf(mx, v[j]); }
    mx = blockReduceMax256(mx);
    float sum = 0.f;
    #pragma unroll
    for (int j = 0; j < 8; j++) { v[j] = __expf(v[j] - mx); sum += v[j]; }
    sum = blockReduceSum256(sum);
    float inv = 1.0f / sum;
    #pragma unroll
    for (int j = 0; j < 8; j++) r[tid + j * 256] = v[j] * inv;
}

__global__ __launch_bounds__(256) void silu_k(
    float* __restrict__ h1, const float* __restrict__ h3, size_t n)
{
    size_t i = (size_t)blockIdx.x * 256 + threadIdx.x;
    if (i >= n) return;
    float a = h1[i];
    float s = a / (1.0f + __expf(-a));
    h1[i] = s * h3[i];
}

// V transpose: v[T][KVC] -> vt[NKV][HD][TT]
__global__ __launch_bounds__(256) void vtrans_k(
    const float* __restrict__ v, float* __restrict__ vt)
{
    __shared__ float tile[32][33];
    int h = blockIdx.z;
    int t0 = blockIdx.x * 32, d0 = blockIdx.y * 32;
    int x = threadIdx.x & 31, y = threadIdx.x >> 5;
    #pragma unroll
    for (int i = y; i < 32; i += 8)
        tile[i][x] = v[(size_t)(t0 + i) * KVC + h * HD + d0 + x];
    __syncthreads();
    #pragma unroll
    for (int i = y; i < 32; i += 8)
        vt[((size_t)h * HD + d0 + i) * TT + t0 + x] = tile[x][i];
}

// =================== tf32 WMMA GEMM =========================================
// C[M,N](+z*sC) = op + A[M,K](+z*sA, lda) * B[N,K]^T(+(z/bdiv)*sB, ldb)
// EPI: 0 -> acc starts at 0
//      1 -> acc starts at I[row][col]   (residual, ld = ldc)
//      2 -> acc starts at I[row][col]   (mask, ld = ldc) + masked-tile early-out
// kcausal: limit K-tiles to (m0+BM)/BK (A causally zero beyond)
#define BM 128
#define BN 128
#define BK 32
#define LDS 36                       // 36 floats = 144B, multiple of 16B
#define SMEM_FLOATS (4 * BM * LDS)   // A(2 bufs) + B(2 bufs)
#define SMEM_BYTES  (SMEM_FLOATS * 4)

__device__ __forceinline__ float to_tf32(float f) {
    float r;
    asm("cvt.rna.tf32.f32 %0, %1;" : "=f"(r) : "f"(f));
    return r;
}

template<int EPI>
__global__ __launch_bounds__(256) void wgemm(
    int M, int N, int K, int kcausal,
    const float* __restrict__ A, int lda, size_t sA,
    const float* __restrict__ B, int ldb, size_t sB, int bdiv,
    float* __restrict__ C, int ldc, size_t sC,
    const float* __restrict__ I)
{
    extern __shared__ float sm[];
    float* As = sm;                       // [2][BM][LDS]
    float* Bs = sm + 2 * BM * LDS;        // [2][BN][LDS]

    int tid = threadIdx.x;
    int m0 = blockIdx.y * BM;
    int n0 = blockIdx.x * BN;
    int z  = blockIdx.z;
    A += (size_t)z * sA;
    B += (size_t)(z / bdiv) * sB;
    C += (size_t)z * sC;

    // Fully-masked score tile: write -1e9 and exit
    if (EPI == 2 && n0 > m0 + BM - 1) {
        float4 neg = make_float4(-1e9f, -1e9f, -1e9f, -1e9f);
        int row = m0 + (tid >> 1);
        float* crow = C + (size_t)row * ldc + n0 + (tid & 1) * 64;
        #pragma unroll
        for (int j = 0; j < 16; j++) *(float4*)(crow + j * 4) = neg;
        return;
    }

    int KT = K / BK;
    if (kcausal) { int lim = (m0 + BM) / BK; if (lim < KT) KT = lim; }

    int wid = tid >> 5;
    int wm = wid & 1;          // 0..1 -> 64-row slab
    int wn = wid >> 1;         // 0..3 -> 32-col slab
    int wrow = m0 + wm * 64;
    int wcol = n0 + wn * 32;

    wmma::fragment<wmma::accumulator, 16, 16, 8, float> acc[4][2];
    #pragma unroll
    for (int mi = 0; mi < 4; mi++)
        #pragma unroll
        for (int ni = 0; ni < 2; ni++) {
            if (EPI == 0) wmma::fill_fragment(acc[mi][ni], 0.0f);
            else wmma::load_matrix_sync(acc[mi][ni],
                     I + (size_t)(wrow + mi * 16) * ldc + wcol + ni * 16,
                     ldc, wmma::mem_row_major);
        }

    // global prefetch mapping: thread -> (row r0+32i, 16B chunk c)
    int c  = tid & 7;          // 8 chunks of 4 floats = 32 floats (BK)
    int r0 = tid >> 3;         // 0..31
    const float* Ap = A + (size_t)(m0 + r0) * lda + c * 4;
    const float* Bp = B + (size_t)(n0 + r0) * ldb + c * 4;

    float4 pa[4], pb[4];
    #pragma unroll
    for (int i = 0; i < 4; i++) {
        pa[i] = *(const float4*)(Ap + (size_t)(32 * i) * lda);
        pb[i] = *(const float4*)(Bp + (size_t)(32 * i) * ldb);
    }
    // commit tile 0
    #pragma unroll
    for (int i = 0; i < 4; i++) {
        float* da = As + (r0 + 32 * i) * LDS + c * 4;
        da[0] = to_tf32(pa[i].x); da[1] = to_tf32(pa[i].y);
        da[2] = to_tf32(pa[i].z); da[3] = to_tf32(pa[i].w);
        float* db = Bs + (r0 + 32 * i) * LDS + c * 4;
        db[0] = to_tf32(pb[i].x); db[1] = to_tf32(pb[i].y);
        db[2] = to_tf32(pb[i].z); db[3] = to_tf32(pb[i].w);
    }
    __syncthreads();

    for (int t = 0; t < KT; t++) {
        int cur = t & 1;
        if (t + 1 < KT) {
            int ko = (t + 1) * BK;
            #pragma unroll
            for (int i = 0; i < 4; i++) {
                pa[i] = *(const float4*)(Ap + (size_t)(32 * i) * lda + ko);
                pb[i] = *(const float4*)(Bp + (size_t)(32 * i) * ldb + ko);
            }
        }

        const float* Ab = As + cur * BM * LDS;
        const float* Bb = Bs + cur * BN * LDS;
        #pragma unroll
        for (int ks = 0; ks < BK / 8; ks++) {
            wmma::fragment<wmma::matrix_a, 16, 16, 8, wmma::precision::tf32, wmma::row_major> af[4];
            wmma::fragment<wmma::matrix_b, 16, 16, 8, wmma::precision::tf32, wmma::col_major> bf[2];
            #pragma unroll
            for (int mi = 0; mi < 4; mi++)
                wmma::load_matrix_sync(af[mi], Ab + (wm * 64 + mi * 16) * LDS + ks * 8, LDS);
            #pragma unroll
            for (int ni = 0; ni < 2; ni++)
                wmma::load_matrix_sync(bf[ni], Bb + (wn * 32 + ni * 16) * LDS + ks * 8, LDS);
            #pragma unroll
            for (int mi = 0; mi < 4; mi++)
                #pragma unroll
                for (int ni = 0; ni < 2; ni++)
                    wmma::mma_sync(acc[mi][ni], af[mi], bf[ni], acc[mi][ni]);
        }

        if (t + 1 < KT) {
            float* Ad = As + (cur ^ 1) * BM * LDS;
            float* Bd = Bs + (cur ^ 1) * BN * LDS;
            #pragma unroll
            for (int i = 0; i < 4; i++) {
                float* da = Ad + (r0 + 32 * i) * LDS + c * 4;
                da[0] = to_tf32(pa[i].x); da[1] = to_tf32(pa[i].y);
                da[2] = to_tf32(pa[i].z); da[3] = to_tf32(pa[i].w);
                float* db = Bd + (r0 + 32 * i) * LDS + c * 4;
                db[0] = to_tf32(pb[i].x); db[1] = to_tf32(pb[i].y);
                db[2] = to_tf32(pb[i].z); db[3] = to_tf32(pb[i].w);
            }
        }
        __syncthreads();
    }

    #pragma unroll
    for (int mi = 0; mi < 4; mi++)
        #pragma unroll
        for (int ni = 0; ni < 2; ni++)
            wmma::store_matrix_sync(
                C + (size_t)(wrow + mi * 16) * ldc + wcol + ni * 16,
                acc[mi][ni], ldc, wmma::mem_row_major);
}

// =================== launch =================================================
extern "C" void kernel_launch(void* const* d_in, const int* in_sizes, int n_in,
                              void* d_out, int out_size)
{
    const float* x    = (const float*)d_in[0];
    const float* fc   = (const float*)d_in[2];
    const float* fs   = (const float*)d_in[3];
    const float* mask = (const float*)d_in[4];
    const float* wq   = (const float*)d_in[5];
    const float* wk   = (const float*)d_in[6];
    const float* wv   = (const float*)d_in[7];
    const float* wo   = (const float*)d_in[8];
    const float* w1   = (const float*)d_in[9];
    const float* w2   = (const float*)d_in[10];
    const float* w3   = (const float*)d_in[11];
    const float* ln1  = (const float*)d_in[12];
    const float* ln2  = (const float*)d_in[13];
    float* out = (float*)d_out;

    float *xn, *q, *k, *v, *vt, *s, *att, *x1, *h1, *h3;
    cudaGetSymbolAddress((void**)&xn,  g_xn);
    cudaGetSymbolAddress((void**)&q,   g_q);
    cudaGetSymbolAddress((void**)&k,   g_k);
    cudaGetSymbolAddress((void**)&v,   g_v);
    cudaGetSymbolAddress((void**)&vt,  g_vt);
    cudaGetSymbolAddress((void**)&s,   g_s);
    cudaGetSymbolAddress((void**)&att, g_att);
    cudaGetSymbolAddress((void**)&x1,  g_x1);
    cudaGetSymbolAddress((void**)&h1,  g_h1);
    cudaGetSymbolAddress((void**)&h3,  g_h3);

    cudaFuncSetAttribute(wgemm<0>, cudaFuncAttributeMaxDynamicSharedMemorySize, SMEM_BYTES);
    cudaFuncSetAttribute(wgemm<1>, cudaFuncAttributeMaxDynamicSharedMemorySize, SMEM_BYTES);
    cudaFuncSetAttribute(wgemm<2>, cudaFuncAttributeMaxDynamicSharedMemorySize, SMEM_BYTES);

    const float iscale = 0.08838834764831843f; // 1/sqrt(128)

    // 1) xn = rmsnorm(x, ln1)
    rmsnorm_k<<<TT, 256>>>(x, ln1, xn);

    // 2-4) q/k/v projections
    wgemm<0><<<dim3(CC / BN,  TT / BM, 1), 256, SMEM_BYTES>>>(
        TT, CC,  CC, 0, xn, CC, 0, wq, CC, 0, 1, q, CC,  0, nullptr);
    wgemm<0><<<dim3(KVC / BN, TT / BM, 1), 256, SMEM_BYTES>>>(
        TT, KVC, CC, 0, xn, CC, 0, wk, CC, 0, 1, k, KVC, 0, nullptr);
    wgemm<0><<<dim3(KVC / BN, TT / BM, 1), 256, SMEM_BYTES>>>(
        TT, KVC, CC, 0, xn, CC, 0, wv, CC, 0, 1, v, KVC, 0, nullptr);

    // 5-6) RoPE on q (scaled by 1/sqrt(HD)), k
    rope_k<<<(TT * NH  * 64 + 255) / 256, 256>>>(q, NH,  fc, fs, iscale);
    rope_k<<<(TT * NKV * 64 + 255) / 256, 256>>>(k, NKV, fc, fs, 1.0f);

    // 6b) transpose V -> vt [NKV][HD][TT]
    vtrans_k<<<dim3(TT / 32, HD / 32, NKV), 256>>>(v, vt);

    // 7) scores[h] = (q*iscale)_h @ k_{h/4}^T + mask   (acc init from mask)
    wgemm<2><<<dim3(TT / BN, TT / BM, NH), 256, SMEM_BYTES>>>(
        TT, TT, HD, 0,
        q, CC, (size_t)HD,
        k, KVC, (size_t)HD, 4,
        s, TT, (size_t)TT * TT,
        mask);

    // 8) softmax rows
    softmax_k<<<NH * TT, 256>>>(s);

    // 9) att[h] = P_h @ vt_{h/4}^T   (causal: skip zero K-tiles)
    wgemm<0><<<dim3(HD / BN, TT / BM, NH), 256, SMEM_BYTES>>>(
        TT, HD, TT, 1,
        s, TT, (size_t)TT * TT,
        vt, TT, (size_t)HD * TT, 4,
        att, CC, (size_t)HD,
        nullptr);

    // 10) x1 = x + att @ wo^T  (acc init from x)
    wgemm<1><<<dim3(CC / BN, TT / BM, 1), 256, SMEM_BYTES>>>(
        TT, CC, CC, 0, att, CC, 0, wo, CC, 0, 1, x1, CC, 0, x);

    // 11) xn2 = rmsnorm(x1, ln2)
    rmsnorm_k<<<TT, 256>>>(x1, ln2, xn);

    // 12-13) h1 = xn2 @ w1^T, h3 = xn2 @ w3^T
    wgemm<0><<<dim3(HID / BN, TT / BM, 1), 256, SMEM_BYTES>>>(
        TT, HID, CC, 0, xn, CC, 0, w1, CC, 0, 1, h1, HID, 0, nullptr);
    wgemm<0><<<dim3(HID / BN, TT / BM, 1), 256, SMEM_BYTES>>>(
        TT, HID, CC, 0, xn, CC, 0, w3, CC, 0, 1, h3, HID, 0, nullptr);

    // 14) h1 = silu(h1) * h3
    {
        size_t n = (size_t)TT * HID;
        silu_k<<<(unsigned)((n + 255) / 256), 256>>>(h1, h3, n);
    }

    // 15) out = x1 + h1 @ w2^T  (acc init from x1)
    wgemm<1><<<dim3(CC / BN, TT / BM, 1), 256, SMEM_BYTES>>>(
        TT, CC, HID, 0, h1, HID, 0, w2, HID, 0, 1, out, CC, 0, x1);
}

// round 5
// speedup vs baseline: 1.7117x; 1.1993x over previous
#include <cuda_runtime.h>
#include <cuda_bf16.h>
#include <mma.h>
#include <cstdint>
#include <math.h>

using namespace nvcuda;

// Problem constants
#define TT   2048
#define CC   4096
#define NH   32
#define NKV  8
#define HD   128
#define KVC  1024
#define HID  11008
#define EPSF 1e-6f

// ---------------- scratch (device globals; no allocation allowed) ----------
__device__ float g_xn [(size_t)TT * CC];
__device__ float g_q  [(size_t)TT * CC];
__device__ float g_k  [(size_t)TT * KVC];
__device__ float g_v  [(size_t)TT * KVC];
__device__ float g_vt [(size_t)NKV * HD * TT];
__device__ float g_s  [(size_t)NH * TT * TT];  // 512MB scores/probs
__device__ float g_att[(size_t)TT * CC];
__device__ float g_x1 [(size_t)TT * CC];
__device__ float g_h1 [(size_t)TT * HID];
__device__ float g_h3 [(size_t)TT * HID];

// =================== elementwise kernels ====================================
__device__ __forceinline__ float blockReduceSum256(float v) {
    __shared__ float sh[8];
    int lane = threadIdx.x & 31, w = threadIdx.x >> 5;
    #pragma unroll
    for (int o = 16; o; o >>= 1) v += __shfl_xor_sync(0xffffffffu, v, o);
    if (lane == 0) sh[w] = v;
    __syncthreads();
    float r = sh[0];
    #pragma unroll
    for (int i = 1; i < 8; i++) r += sh[i];
    return r;
}
__device__ __forceinline__ float blockReduceMax256(float v) {
    __shared__ float sh[8];
    int lane = threadIdx.x & 31, w = threadIdx.x >> 5;
    #pragma unroll
    for (int o = 16; o; o >>= 1) v = fmaxf(v, __shfl_xor_sync(0xffffffffu, v, o));
    if (lane == 0) sh[w] = v;
    __syncthreads();
    float r = sh[0];
    #pragma unroll
    for (int i = 1; i < 8; i++) r = fmaxf(r, sh[i]);
    return r;
}

__global__ __launch_bounds__(256) void rmsnorm_k(
    const float* __restrict__ x, const float* __restrict__ w, float* __restrict__ out)
{
    size_t t = blockIdx.x;
    const float* xr = x + t * CC;
    float ss = 0.f;
    for (int i = threadIdx.x; i < CC; i += 256) { float v = xr[i]; ss += v * v; }
    float tot = blockReduceSum256(ss);
    float inv = rsqrtf(tot * (1.0f / CC) + EPSF);
    for (int i = threadIdx.x; i < CC; i += 256)
        out[t * CC + i] = xr[i] * inv * w[i];
}

// RoPE with optional output scale (folds 1/sqrt(HD) into q)
__global__ __launch_bounds__(256) void rope_k(
    float* __restrict__ q, int nheads,
    const float* __restrict__ fc, const float* __restrict__ fs, float oscale)
{
    int idx = blockIdx.x * 256 + threadIdx.x;
    int total = TT * nheads * (HD / 2);
    if (idx >= total) return;
    int i = idx & 63;
    int h = (idx >> 6) % nheads;
    int t = idx / (64 * nheads);
    float c = fc[t * 64 + i], s = fs[t * 64 + i];
    float* p = q + (size_t)t * nheads * HD + h * HD + 2 * i;
    float re = p[0], im = p[1];
    p[0] = (re * c - im * s) * oscale;
    p[1] = (re * s + im * c) * oscale;
}

// softmax over causal-padded row length Lpad = (t/128+1)*128; columns >= Lpad
// are never written nor read downstream.
__global__ __launch_bounds__(256) void softmax_k(float* __restrict__ S)
{
    size_t row = blockIdx.x;
    int t = (int)(row & (TT - 1));
    int Lpad = ((t >> 7) << 7) + 128;
    float* r = S + row * TT;
    int tid = threadIdx.x;
    float v[8];
    float mx = -1e30f;
    #pragma unroll
    for (int j = 0; j < 8; j++) {
        int idx = tid + j * 256;
        v[j] = (idx < Lpad) ? r[idx] : -1e30f;
        mx = fmaxf(mx, v[j]);
    }
    mx = blockReduceMax256(mx);
    float sum = 0.f;
    #pragma unroll
    for (int j = 0; j < 8; j++) { v[j] = __expf(v[j] - mx); sum += v[j]; }
    sum = blockReduceSum256(sum);
    float inv = 1.0f / sum;
    #pragma unroll
    for (int j = 0; j < 8; j++) {
        int idx = tid + j * 256;
        if (idx < Lpad) r[idx] = v[j] * inv;
    }
}

__global__ __launch_bounds__(256) void silu_k(
    float* __restrict__ h1, const float* __restrict__ h3, size_t n)
{
    size_t i = (size_t)blockIdx.x * 256 + threadIdx.x;
    if (i >= n) return;
    float a = h1[i];
    float s = a / (1.0f + __expf(-a));
    h1[i] = s * h3[i];
}

// V transpose: v[T][KVC] -> vt[NKV][HD][TT]
__global__ __launch_bounds__(256) void vtrans_k(
    const float* __restrict__ v, float* __restrict__ vt)
{
    __shared__ float tile[32][33];
    int h = blockIdx.z;
    int t0 = blockIdx.x * 32, d0 = blockIdx.y * 32;
    int x = threadIdx.x & 31, y = threadIdx.x >> 5;
    #pragma unroll
    for (int i = y; i < 32; i += 8)
        tile[i][x] = v[(size_t)(t0 + i) * KVC + h * HD + d0 + x];
    __syncthreads();
    #pragma unroll
    for (int i = y; i < 32; i += 8)
        vt[((size_t)h * HD + d0 + i) * TT + t0 + x] = tile[x][i];
}

// =================== tf32 WMMA GEMM (cp.async 3-stage) ======================
#define BM 128
#define BN 128
#define BK 32
#define LDS 36
#define NSTAGE 3
#define STAGE_FLOATS (2 * BM * LDS)          // A + B per stage
#define SMEM_BYTES (NSTAGE * STAGE_FLOATS * 4)

__device__ __forceinline__ float to_tf32(float f) {
    float r;
    asm("cvt.rna.tf32.f32 %0, %1;" : "=f"(r) : "f"(f));
    return r;
}
__device__ __forceinline__ uint32_t smem_u32(const void* p) {
    uint32_t a;
    asm("{ .reg .u64 t; cvta.to.shared.u64 t, %1; cvt.u32.u64 %0, t; }" : "=r"(a) : "l"(p));
    return a;
}
__device__ __forceinline__ void cp16(uint32_t dst, const void* src) {
    asm volatile("cp.async.cg.shared.global [%0], [%1], 16;" :: "r"(dst), "l"(src));
}
#define CP_COMMIT()  asm volatile("cp.async.commit_group;" ::: "memory")
#define CP_WAIT(n)   asm volatile("cp.async.wait_group %0;" :: "n"(n) : "memory")

// C[M,N](+z*sC) = init + A[M,K](+z*sA, lda) * B[N,K]^T(+(z/bdiv)*sB, ldb)
// EPI: 0 acc=0 | 1 acc=I (residual) | 2 acc=I (mask) + masked-tile skip (no store)
// kcausal: limit K-tiles to (m0+BM)/BK
template<int EPI>
__global__ __launch_bounds__(256, 2) void wgemm(
    int M, int N, int K, int kcausal,
    const float* __restrict__ A, int lda, size_t sA,
    const float* __restrict__ B, int ldb, size_t sB, int bdiv,
    float* __restrict__ C, int ldc, size_t sC,
    const float* __restrict__ I)
{
    extern __shared__ float sm[];
    int tid = threadIdx.x;
    int m0 = blockIdx.y * BM;
    int n0 = blockIdx.x * BN;
    int z  = blockIdx.z;
    A += (size_t)z * sA;
    B += (size_t)(z / bdiv) * sB;
    C += (size_t)z * sC;

    // Fully-masked score tile: nothing downstream reads it -> skip entirely
    if (EPI == 2 && n0 > m0 + BM - 1) return;

    int KT = K / BK;
    if (kcausal) { int lim = (m0 + BM) / BK; if (lim < KT) KT = lim; }

    int wid = tid >> 5;
    int wm = wid & 1;          // 64-row slab
    int wn = wid >> 1;         // 32-col slab
    int wrow = m0 + wm * 64;
    int wcol = n0 + wn * 32;

    wmma::fragment<wmma::accumulator, 16, 16, 8, float> acc[4][2];
    #pragma unroll
    for (int mi = 0; mi < 4; mi++)
        #pragma unroll
        for (int ni = 0; ni < 2; ni++) {
            if (EPI == 0) wmma::fill_fragment(acc[mi][ni], 0.0f);
            else wmma::load_matrix_sync(acc[mi][ni],
                     I + (size_t)(wrow + mi * 16) * ldc + wcol + ni * 16,
                     ldc, wmma::mem_row_major);
        }

    // cp.async mapping: c = 16B chunk (8 per row), r0 = row group
    int c  = tid & 7;
    int r0 = tid >> 3;         // 0..31
    uint32_t sbase = smem_u32(sm);
    const float* Ap = A + (size_t)(m0 + r0) * lda + c * 4;
    const float* Bp = B + (size_t)(n0 + r0) * ldb + c * 4;

    auto issue_stage = [&](int buf, int t) {
        uint32_t as = sbase + (uint32_t)(buf * STAGE_FLOATS) * 4u;
        uint32_t bs = as + (uint32_t)(BM * LDS) * 4u;
        int ko = t * BK;
        #pragma unroll
        for (int i = 0; i < 4; i++) {
            uint32_t soff = (uint32_t)((r0 + 32 * i) * LDS + c * 4) * 4u;
            cp16(as + soff, Ap + (size_t)(32 * i) * lda + ko);
            cp16(bs + soff, Bp + (size_t)(32 * i) * ldb + ko);
        }
        CP_COMMIT();
    };

    issue_stage(0, 0);
    if (KT > 1) issue_stage(1, 1);

    for (int t = 0; t < KT; t++) {
        if (t + 2 < KT) issue_stage((t + 2) % NSTAGE, t + 2);

        if (t + 2 < KT)      CP_WAIT(2);
        else if (t + 1 < KT) CP_WAIT(1);
        else                 CP_WAIT(0);
        __syncthreads();

        const float* Ab = sm + (t % NSTAGE) * STAGE_FLOATS;
        const float* Bb = Ab + BM * LDS;
        #pragma unroll
        for (int ks = 0; ks < BK / 8; ks++) {
            wmma::fragment<wmma::matrix_a, 16, 16, 8, wmma::precision::tf32, wmma::row_major> af[4];
            wmma::fragment<wmma::matrix_b, 16, 16, 8, wmma::precision::tf32, wmma::col_major> bf[2];
            #pragma unroll
            for (int mi = 0; mi < 4; mi++) {
                wmma::load_matrix_sync(af[mi], Ab + (wm * 64 + mi * 16) * LDS + ks * 8, LDS);
                #pragma unroll
                for (int e = 0; e < af[mi].num_elements; e++)
                    af[mi].x[e] = to_tf32(af[mi].x[e]);
            }
            #pragma unroll
            for (int ni = 0; ni < 2; ni++) {
                wmma::load_matrix_sync(bf[ni], Bb + (wn * 32 + ni * 16) * LDS + ks * 8, LDS);
                #pragma unroll
                for (int e = 0; e < bf[ni].num_elements; e++)
                    bf[ni].x[e] = to_tf32(bf[ni].x[e]);
            }
            #pragma unroll
            for (int mi = 0; mi < 4; mi++)
                #pragma unroll
                for (int ni = 0; ni < 2; ni++)
                    wmma::mma_sync(acc[mi][ni], af[mi], bf[ni], acc[mi][ni]);
        }
        __syncthreads();
    }

    #pragma unroll
    for (int mi = 0; mi < 4; mi++)
        #pragma unroll
        for (int ni = 0; ni < 2; ni++)
            wmma::store_matrix_sync(
                C + (size_t)(wrow + mi * 16) * ldc + wcol + ni * 16,
                acc[mi][ni], ldc, wmma::mem_row_major);
}

// =================== launch =================================================
extern "C" void kernel_launch(void* const* d_in, const int* in_sizes, int n_in,
                              void* d_out, int out_size)
{
    const float* x    = (const float*)d_in[0];
    const float* fc   = (const float*)d_in[2];
    const float* fs   = (const float*)d_in[3];
    const float* mask = (const float*)d_in[4];
    const float* wq   = (const float*)d_in[5];
    const float* wk   = (const float*)d_in[6];
    const float* wv   = (const float*)d_in[7];
    const float* wo   = (const float*)d_in[8];
    const float* w1   = (const float*)d_in[9];
    const float* w2   = (const float*)d_in[10];
    const float* w3   = (const float*)d_in[11];
    const float* ln1  = (const float*)d_in[12];
    const float* ln2  = (const float*)d_in[13];
    float* out = (float*)d_out;

    float *xn, *q, *k, *v, *vt, *s, *att, *x1, *h1, *h3;
    cudaGetSymbolAddress((void**)&xn,  g_xn);
    cudaGetSymbolAddress((void**)&q,   g_q);
    cudaGetSymbolAddress((void**)&k,   g_k);
    cudaGetSymbolAddress((void**)&v,   g_v);
    cudaGetSymbolAddress((void**)&vt,  g_vt);
    cudaGetSymbolAddress((void**)&s,   g_s);
    cudaGetSymbolAddress((void**)&att, g_att);
    cudaGetSymbolAddress((void**)&x1,  g_x1);
    cudaGetSymbolAddress((void**)&h1,  g_h1);
    cudaGetSymbolAddress((void**)&h3,  g_h3);

    cudaFuncSetAttribute(wgemm<0>, cudaFuncAttributeMaxDynamicSharedMemorySize, SMEM_BYTES);
    cudaFuncSetAttribute(wgemm<1>, cudaFuncAttributeMaxDynamicSharedMemorySize, SMEM_BYTES);
    cudaFuncSetAttribute(wgemm<2>, cudaFuncAttributeMaxDynamicSharedMemorySize, SMEM_BYTES);

    const float iscale = 0.08838834764831843f; // 1/sqrt(128)

    // 1) xn = rmsnorm(x, ln1)
    rmsnorm_k<<<TT, 256>>>(x, ln1, xn);

    // 2-4) q/k/v projections
    wgemm<0><<<dim3(CC / BN,  TT / BM, 1), 256, SMEM_BYTES>>>(
        TT, CC,  CC, 0, xn, CC, 0, wq, CC, 0, 1, q, CC,  0, nullptr);
    wgemm<0><<<dim3(KVC / BN, TT / BM, 1), 256, SMEM_BYTES>>>(
        TT, KVC, CC, 0, xn, CC, 0, wk, CC, 0, 1, k, KVC, 0, nullptr);
    wgemm<0><<<dim3(KVC / BN, TT / BM, 1), 256, SMEM_BYTES>>>(
        TT, KVC, CC, 0, xn, CC, 0, wv, CC, 0, 1, v, KVC, 0, nullptr);

    // 5-6) RoPE on q (scaled by 1/sqrt(HD)), k
    rope_k<<<(TT * NH  * 64 + 255) / 256, 256>>>(q, NH,  fc, fs, iscale);
    rope_k<<<(TT * NKV * 64 + 255) / 256, 256>>>(k, NKV, fc, fs, 1.0f);

    // 6b) transpose V -> vt [NKV][HD][TT]
    vtrans_k<<<dim3(TT / 32, HD / 32, NKV), 256>>>(v, vt);

    // 7) scores[h] = (q*iscale)_h @ k_{h/4}^T + mask (acc init from mask; masked tiles skipped)
    wgemm<2><<<dim3(TT / BN, TT / BM, NH), 256, SMEM_BYTES>>>(
        TT, TT, HD, 0,
        q, CC, (size_t)HD,
        k, KVC, (size_t)HD, 4,
        s, TT, (size_t)TT * TT,
        mask);

    // 8) softmax rows (causal length only)
    softmax_k<<<NH * TT, 256>>>(s);

    // 9) att[h] = P_h @ vt_{h/4}^T   (causal: skip zero K-tiles)
    wgemm<0><<<dim3(HD / BN, TT / BM, NH), 256, SMEM_BYTES>>>(
        TT, HD, TT, 1,
        s, TT, (size_t)TT * TT,
        vt, TT, (size_t)HD * TT, 4,
        att, CC, (size_t)HD,
        nullptr);

    // 10) x1 = x + att @ wo^T  (acc init from x)
    wgemm<1><<<dim3(CC / BN, TT / BM, 1), 256, SMEM_BYTES>>>(
        TT, CC, CC, 0, att, CC, 0, wo, CC, 0, 1, x1, CC, 0, x);

    // 11) xn2 = rmsnorm(x1, ln2)
    rmsnorm_k<<<TT, 256>>>(x1, ln2, xn);

    // 12-13) h1 = xn2 @ w1^T, h3 = xn2 @ w3^T
    wgemm<0><<<dim3(HID / BN, TT / BM, 1), 256, SMEM_BYTES>>>(
        TT, HID, CC, 0, xn, CC, 0, w1, CC, 0, 1, h1, HID, 0, nullptr);
    wgemm<0><<<dim3(HID / BN, TT / BM, 1), 256, SMEM_BYTES>>>(
        TT, HID, CC, 0, xn, CC, 0, w3, CC, 0, 1, h3, HID, 0, nullptr);

    // 14) h1 = silu(h1) * h3
    {
        size_t n = (size_t)TT * HID;
        silu_k<<<(unsigned)((n + 255) / 256), 256>>>(h1, h3, n);
    }

    // 15) out = x1 + h1 @ w2^T  (acc init from x1)
    wgemm<1><<<dim3(CC / BN, TT / BM, 1), 256, SMEM_BYTES>>>(
        TT, CC, HID, 0, h1, HID, 0, w2, HID, 0, 1, out, CC, 0, x1);
}